// round 5
// baseline (speedup 1.0000x reference)
#include <cuda_runtime.h>

// Problem constants
#define BSZ 2
#define HN  8
#define TN  2048
#define NN  256
#define NCH 8      // chunks along T
#define CSZ 256    // chunk size

// Scratch (static device globals; allocation-free per harness rules)
__device__ float g_A[BSZ*HN*TN*NN];        // A = R @ Q_h        [b,h,t,j]
__device__ float g_W[BSZ*HN*TN*NN];        // W = R @ E_h^T      [b,h,u,i]
__device__ float g_G[BSZ*HN*NCH*NN*NN];    // per-chunk state    [b,h,c,j,i]
__device__ float g_S[BSZ*HN*NCH*NN*NN];    // exclusive prefix   [b,h,c,j,i]
__device__ float g_P[BSZ*HN*NCH*NN*NN];    // masked intra-chunk [b,h,c,t,u]
__device__ float g_O[BSZ*HN*TN*NN];        // per-head output    [b,h,t,i]

// ---------------------------------------------------------------------------
// 128x128x16 fp32 GEMM tile core, 256 threads, 8x8 per thread.
// Double-buffered smem with register-staged prefetch: one __syncthreads per
// K-step; next tile's global loads are issued before the current compute so
// their latency hides behind 16x64 FFMAs per thread.
// TA: A is stored (K x M) row-major. TB: B is stored (N x K) row-major.
// MODE: 0 = C = A*B ; 1 = C += A*B ; 2 = C = tril(A*B) (col <= row kept)
// All dims are multiples of the tile sizes for this problem.
// ---------------------------------------------------------------------------
template<bool TA, bool TB, int MODE>
__device__ __forceinline__ void gemm_core(
    const float* __restrict__ A, int lda,
    const float* __restrict__ B, int ldb,
    float* __restrict__ C, int ldc,
    int K)
{
    constexpr int BM = 128, BN = 128, BK = 16;
    // __align__(16): these are read with float4 (LDS.128); base must be 16B
    // aligned or the loads trap. Row stride (BM+4)=132 floats = 528B = 33*16.
    __shared__ __align__(16) float As[2][BK][BM + 4];
    __shared__ __align__(16) float Bs[2][BK][BN + 4];

    const int tid = threadIdx.x;
    const int m0 = blockIdx.y * BM;
    const int n0 = blockIdx.x * BN;
    const int tx = tid & 15;
    const int ty = tid >> 4;

    if (MODE == 2 && n0 >= m0 + BM) {
        // tile entirely above the diagonal -> zeros
        #pragma unroll
        for (int i = 0; i < 8; i++)
            #pragma unroll
            for (int j = 0; j < 8; j++)
                C[(size_t)(m0 + ty*8 + i) * ldc + (n0 + tx*8 + j)] = 0.f;
        return;
    }

    float acc[8][8];
    #pragma unroll
    for (int i = 0; i < 8; i++)
        #pragma unroll
        for (int j = 0; j < 8; j++)
            acc[i][j] = 0.f;

    // ---- helpers: gather one tile's worth of data into registers ----
    auto fetch_a = [&](int k0, float (&ra)[8]) {
        if (!TA) {
            const int lk = tid & 15;
            const int mb = tid >> 4;
            #pragma unroll
            for (int i = 0; i < 8; i++)
                ra[i] = A[(size_t)(m0 + mb * 8 + i) * lda + (k0 + lk)];
        } else {
            const int col = tid & 127;
            const int rb  = tid >> 7;
            #pragma unroll
            for (int i = 0; i < 8; i++)
                ra[i] = A[(size_t)(k0 + rb * 8 + i) * lda + (m0 + col)];
        }
    };
    auto fetch_b = [&](int k0, float (&rb_)[8]) {
        if (!TB) {
            const int col = tid & 127;
            const int rb  = tid >> 7;
            #pragma unroll
            for (int i = 0; i < 8; i++)
                rb_[i] = B[(size_t)(k0 + rb * 8 + i) * ldb + (n0 + col)];
        } else {
            const int lk = tid & 15;
            const int nb = tid >> 4;
            #pragma unroll
            for (int i = 0; i < 8; i++)
                rb_[i] = B[(size_t)(n0 + nb * 8 + i) * ldb + (k0 + lk)];
        }
    };
    auto store_a = [&](int buf, const float (&ra)[8]) {
        if (!TA) {
            const int lk = tid & 15;
            const int mb = tid >> 4;
            #pragma unroll
            for (int i = 0; i < 8; i++)
                As[buf][lk][mb * 8 + i] = ra[i];
        } else {
            const int col = tid & 127;
            const int rb  = tid >> 7;
            #pragma unroll
            for (int i = 0; i < 8; i++)
                As[buf][rb * 8 + i][col] = ra[i];
        }
    };
    auto store_b = [&](int buf, const float (&rb_)[8]) {
        if (!TB) {
            const int col = tid & 127;
            const int rb  = tid >> 7;
            #pragma unroll
            for (int i = 0; i < 8; i++)
                Bs[buf][rb * 8 + i][col] = rb_[i];
        } else {
            const int lk = tid & 15;
            const int nb = tid >> 4;
            #pragma unroll
            for (int i = 0; i < 8; i++)
                Bs[buf][lk][nb * 8 + i] = rb_[i];
        }
    };

    // ---- prologue: load first tile into buffer 0 ----
    {
        float ra[8], rb_[8];
        fetch_a(0, ra);
        fetch_b(0, rb_);
        store_a(0, ra);
        store_b(0, rb_);
    }
    __syncthreads();

    int buf = 0;
    for (int k0 = 0; k0 < K; k0 += BK) {
        const bool has_next = (k0 + BK) < K;
        float ra[8], rb_[8];
        if (has_next) {          // issue next tile's global loads FIRST
            fetch_a(k0 + BK, ra);
            fetch_b(k0 + BK, rb_);
        }

        // compute on current buffer while loads are in flight
        #pragma unroll
        for (int kk = 0; kk < BK; kk++) {
            const float4 a0 = *reinterpret_cast<const float4*>(&As[buf][kk][ty * 8]);
            const float4 a1 = *reinterpret_cast<const float4*>(&As[buf][kk][ty * 8 + 4]);
            const float4 b0 = *reinterpret_cast<const float4*>(&Bs[buf][kk][tx * 8]);
            const float4 b1 = *reinterpret_cast<const float4*>(&Bs[buf][kk][tx * 8 + 4]);
            const float a[8] = {a0.x, a0.y, a0.z, a0.w, a1.x, a1.y, a1.z, a1.w};
            const float b[8] = {b0.x, b0.y, b0.z, b0.w, b1.x, b1.y, b1.z, b1.w};
            #pragma unroll
            for (int i = 0; i < 8; i++)
                #pragma unroll
                for (int j = 0; j < 8; j++)
                    acc[i][j] += a[i] * b[j];
        }

        if (has_next) {
            store_a(buf ^ 1, ra);
            store_b(buf ^ 1, rb_);
            __syncthreads();
            buf ^= 1;
        }
    }

    // ---- epilogue ----
    #pragma unroll
    for (int i = 0; i < 8; i++) {
        const int row = m0 + ty * 8 + i;
        #pragma unroll
        for (int j = 0; j < 8; j++) {
            const int col = n0 + tx * 8 + j;
            const size_t idx = (size_t)row * ldc + col;
            float v = acc[i][j];
            if (MODE == 2) v = (col <= row) ? v : 0.f;
            if (MODE == 1) C[idx] += v;
            else           C[idx] = v;
        }
    }
}

// ---------------------------------------------------------------------------
// Step kernels (thin wrappers computing batch pointers)
// ---------------------------------------------------------------------------

// A[b,h] = R[b] (2048x256) @ Q[h] (256x256)          grid (2,16,16)
__global__ void __launch_bounds__(256) k_gemm_A(const float* __restrict__ R,
                                                const float* __restrict__ Q) {
    const int z = blockIdx.z, b = z >> 3, h = z & 7;
    gemm_core<false, false, 0>(R + (size_t)b * TN * NN, NN,
                               Q + (size_t)h * NN * NN, NN,
                               g_A + (size_t)z * TN * NN, NN, NN);
}

// W[b,h] = R[b] @ E[h]^T                             grid (2,16,16)
__global__ void __launch_bounds__(256) k_gemm_W(const float* __restrict__ R,
                                                const float* __restrict__ E) {
    const int z = blockIdx.z, b = z >> 3, h = z & 7;
    gemm_core<false, true, 0>(R + (size_t)b * TN * NN, NN,
                              E + (size_t)h * NN * NN, NN,
                              g_W + (size_t)z * TN * NN, NN, NN);
}

// G[b,h,c] = R_c^T (256x256, K=u) @ W_c              grid (2,2,128)
__global__ void __launch_bounds__(256) k_gemm_G(const float* __restrict__ R) {
    const int z = blockIdx.z, b = z >> 6, h = (z >> 3) & 7, c = z & 7;
    gemm_core<true, false, 0>(R + ((size_t)b * TN + (size_t)c * CSZ) * NN, NN,
                              g_W + ((size_t)(b * HN + h) * TN + (size_t)c * CSZ) * NN, NN,
                              g_G + (size_t)z * NN * NN, NN, CSZ);
}

// S[b,h,c] = sum_{c' < c} G[b,h,c']  (exclusive prefix over 8 chunks)
__global__ void k_prefix() {
    const size_t gid = (size_t)blockIdx.x * 256 + threadIdx.x; // < B*H*256*256
    const size_t bh = gid >> 16;
    const size_t e  = gid & 65535;
    float run = 0.f;
    #pragma unroll
    for (int c = 0; c < NCH; c++) {
        const size_t idx = (bh * NCH + c) * 65536 + e;
        g_S[idx] = run;
        run += g_G[idx];
    }
}

// O[b,h,c] = A_c @ S_c   (inter-chunk contribution)  grid (2,2,128)
__global__ void __launch_bounds__(256) k_gemm_O1() {
    const int z = blockIdx.z, b = z >> 6, h = (z >> 3) & 7, c = z & 7;
    const size_t row = ((size_t)(b * HN + h) * TN + (size_t)c * CSZ) * NN;
    gemm_core<false, false, 0>(g_A + row, NN,
                               g_S + (size_t)z * NN * NN, NN,
                               g_O + row, NN, NN);
}

// P[b,h,c] = tril(A_c @ R_c^T)                       grid (2,2,128)
__global__ void __launch_bounds__(256) k_gemm_P(const float* __restrict__ R) {
    const int z = blockIdx.z, b = z >> 6, h = (z >> 3) & 7, c = z & 7;
    gemm_core<false, true, 2>(g_A + ((size_t)(b * HN + h) * TN + (size_t)c * CSZ) * NN, NN,
                              R + ((size_t)b * TN + (size_t)c * CSZ) * NN, NN,
                              g_P + (size_t)z * NN * NN, NN, NN);
}

// O[b,h,c] += P @ W_c   (intra-chunk contribution)   grid (2,2,128)
__global__ void __launch_bounds__(256) k_gemm_O2() {
    const int z = blockIdx.z, b = z >> 6, h = (z >> 3) & 7, c = z & 7;
    const size_t row = ((size_t)(b * HN + h) * TN + (size_t)c * CSZ) * NN;
    gemm_core<false, false, 1>(g_P + (size_t)z * NN * NN, NN,
                               g_W + row, NN,
                               g_O + row, NN, CSZ);
}

// out[b,t,i] = sum_h O[b,h,t,i]
__global__ void k_reduce(float* __restrict__ out) {
    const size_t gid = (size_t)blockIdx.x * 256 + threadIdx.x; // < B*T*N
    const size_t b = gid / ((size_t)TN * NN);
    const size_t rem = gid % ((size_t)TN * NN);
    float s = 0.f;
    #pragma unroll
    for (int h = 0; h < HN; h++)
        s += g_O[((b * HN + h) * (size_t)TN * NN) + rem];
    out[gid] = s;
}

// ---------------------------------------------------------------------------
extern "C" void kernel_launch(void* const* d_in, const int* in_sizes, int n_in,
                              void* d_out, int out_size) {
    const float* R = (const float*)d_in[0];   // r_prime [2,2048,256]
    const float* Q = (const float*)d_in[1];   // Q       [8,256,256]
    const float* E = (const float*)d_in[2];   // E       [8,256,256]
    float* out = (float*)d_out;               // r       [2,2048,256]

    const dim3 blk(256);
    const dim3 grid_big(NN / 128, TN / 128, BSZ * HN);      // (2,16,16)
    const dim3 grid_sq(NN / 128, NN / 128, BSZ * HN * NCH); // (2,2,128)

    k_gemm_A<<<grid_big, blk>>>(R, Q);
    k_gemm_W<<<grid_big, blk>>>(R, E);
    k_gemm_G<<<grid_sq, blk>>>(R);
    k_prefix<<<(BSZ * HN * NN * NN) / 256, blk>>>();
    k_gemm_O1<<<grid_sq, blk>>>();
    k_gemm_P<<<grid_sq, blk>>>(R);
    k_gemm_O2<<<grid_sq, blk>>>();
    k_reduce<<<(BSZ * TN * NN) / 256, blk>>>(out);
}

// round 9
// speedup vs baseline: 2.4053x; 2.4053x over previous
#include <cuda_runtime.h>
#include <cuda_bf16.h>
#include <cstdint>

// Problem constants
#define BSZ 2
#define HN  8
#define TN  2048
#define NN  256
#define NCH 8      // chunks along T
#define CSZ 256    // chunk size

typedef __nv_bfloat16 bf16;

// ---------------------------------------------------------------------------
// Scratch (static device globals). All GEMM operands are bf16 split pairs
// (hi/lo) laid out so that EVERY mma operand is k-contiguous:
//   A-side tiles read [M][K], B-side tiles read [N][K] (i.e. Y^T row-major).
// __align__(16): cp.async.cg ..., 16 requires 16B-aligned gmem addresses and
// the epilogues use bfloat162/float2 stores; base alignment must be >= 16.
// ---------------------------------------------------------------------------
__device__ __align__(16) bf16 g_Rh [BSZ*TN*NN], g_Rl [BSZ*TN*NN];   // R  [b][t][i]
__device__ __align__(16) bf16 g_Rth[BSZ*NN*TN], g_Rtl[BSZ*NN*TN];   // R^T [b][i][t]
__device__ __align__(16) bf16 g_Qth[HN*NN*NN],  g_Qtl[HN*NN*NN];    // Q^T [h][j][i]
__device__ __align__(16) bf16 g_Eh [HN*NN*NN],  g_El [HN*NN*NN];    // E  [h][i][k]
__device__ __align__(16) bf16 g_Ah [BSZ*HN*TN*NN], g_Al [BSZ*HN*TN*NN]; // A=RQ [bh][t][j]
__device__ __align__(16) bf16 g_Wth[BSZ*HN*NN*TN], g_Wtl[BSZ*HN*NN*TN]; // W^T [bh][i][u]
__device__ __align__(16) float g_Gt[BSZ*HN*NCH*NN*NN];                  // G^T [bhc][i][j]
__device__ __align__(16) bf16 g_Sth[BSZ*HN*NCH*NN*NN], g_Stl[BSZ*HN*NCH*NN*NN]; // S^T
__device__ __align__(16) bf16 g_Ph [BSZ*HN*NCH*NN*NN], g_Pl [BSZ*HN*NCH*NN*NN]; // P
__device__ __align__(16) float g_O[BSZ*HN*TN*NN];                       // per-head out

// ---------------------------------------------------------------------------
// Helpers
// ---------------------------------------------------------------------------
__device__ __forceinline__ void split2(float v, bf16& h, bf16& l) {
    h = __float2bfloat16(v);
    l = __float2bfloat16(v - __bfloat162float(h));
}

__device__ __forceinline__ void cp16(void* sptr, const void* gptr) {
    uint32_t s = (uint32_t)__cvta_generic_to_shared(sptr);
    asm volatile("cp.async.cg.shared.global [%0], [%1], 16;\n"
                 :: "r"(s), "l"(gptr) : "memory");
}

__device__ __forceinline__ void mma16816(float c[4], const uint32_t a[4],
                                         const uint32_t b[2]) {
    asm volatile(
        "mma.sync.aligned.m16n8k16.row.col.f32.bf16.bf16.f32 "
        "{%0,%1,%2,%3},{%4,%5,%6,%7},{%8,%9},{%0,%1,%2,%3};\n"
        : "+f"(c[0]), "+f"(c[1]), "+f"(c[2]), "+f"(c[3])
        : "r"(a[0]), "r"(a[1]), "r"(a[2]), "r"(a[3]), "r"(b[0]), "r"(b[1]));
}

// Shared staging: 4 arrays (Xh,Xl,Yh,Yl), 2 stages, 128 rows x 16 k (pitch 24
// bf16 = 48B). Total = 4*2*128*24*2B = 49152B (static 48KB limit, exactly).
struct __align__(16) SB {
    bf16 xh[2][128][24];
    bf16 xl[2][128][24];
    bf16 yh[2][128][24];
    bf16 yl[2][128][24];
};

// ---------------------------------------------------------------------------
// Mainloop: C128x128 += (Xh+Xl)(Yh+Yl)^T dropping Xl*Yl.
// X*: [128][K] at tile row origin (ld = ldx). Y*: [128][K] at tile col origin.
// 256 threads = 8 warps (4m x 2n), warp tile 32x64. cp.async double-buffered.
// ---------------------------------------------------------------------------
__device__ __forceinline__ void gemm_ml(
    float acc[2][8][4], SB* sb,
    const bf16* __restrict__ Xh, const bf16* __restrict__ Xl, int ldx,
    const bf16* __restrict__ Yh, const bf16* __restrict__ Yl, int ldy,
    int K)
{
    const int tid  = threadIdx.x;
    const int row  = tid >> 1, cpos = tid & 1;   // staging map
    const int lane = tid & 31, wid  = tid >> 5;
    const int g = lane >> 2, t = lane & 3;
    const int wm = (wid >> 1) * 32, wn = (wid & 1) * 64;

    auto issue = [&](int s, int k0) {
        cp16(&sb->xh[s][row][cpos * 8], Xh + (size_t)row * ldx + k0 + cpos * 8);
        cp16(&sb->xl[s][row][cpos * 8], Xl + (size_t)row * ldx + k0 + cpos * 8);
        cp16(&sb->yh[s][row][cpos * 8], Yh + (size_t)row * ldy + k0 + cpos * 8);
        cp16(&sb->yl[s][row][cpos * 8], Yl + (size_t)row * ldy + k0 + cpos * 8);
        asm volatile("cp.async.commit_group;\n" ::: "memory");
    };

    issue(0, 0);
    int buf = 0;
    for (int k0 = 0; k0 < K; k0 += 16) {
        asm volatile("cp.async.wait_group 0;\n" ::: "memory");
        __syncthreads();
        if (k0 + 16 < K) issue(buf ^ 1, k0 + 16);

        // A fragments (hi & lo) for both 16-row m-blocks
        uint32_t ah[2][4], al[2][4];
        #pragma unroll
        for (int mb = 0; mb < 2; mb++) {
            const int r = wm + mb * 16 + g;
            ah[mb][0] = *(const uint32_t*)&sb->xh[buf][r    ][t * 2];
            ah[mb][1] = *(const uint32_t*)&sb->xh[buf][r + 8][t * 2];
            ah[mb][2] = *(const uint32_t*)&sb->xh[buf][r    ][t * 2 + 8];
            ah[mb][3] = *(const uint32_t*)&sb->xh[buf][r + 8][t * 2 + 8];
            al[mb][0] = *(const uint32_t*)&sb->xl[buf][r    ][t * 2];
            al[mb][1] = *(const uint32_t*)&sb->xl[buf][r + 8][t * 2];
            al[mb][2] = *(const uint32_t*)&sb->xl[buf][r    ][t * 2 + 8];
            al[mb][3] = *(const uint32_t*)&sb->xl[buf][r + 8][t * 2 + 8];
        }
        // B fragments in two halves of 4 n-blocks (register pressure)
        #pragma unroll
        for (int half = 0; half < 2; half++) {
            uint32_t bh_[4][2], bl_[4][2];
            #pragma unroll
            for (int q = 0; q < 4; q++) {
                const int rn = wn + (half * 4 + q) * 8 + g;
                bh_[q][0] = *(const uint32_t*)&sb->yh[buf][rn][t * 2];
                bh_[q][1] = *(const uint32_t*)&sb->yh[buf][rn][t * 2 + 8];
                bl_[q][0] = *(const uint32_t*)&sb->yl[buf][rn][t * 2];
                bl_[q][1] = *(const uint32_t*)&sb->yl[buf][rn][t * 2 + 8];
            }
            #pragma unroll
            for (int mb = 0; mb < 2; mb++)
                #pragma unroll
                for (int q = 0; q < 4; q++) {
                    float* c = acc[mb][half * 4 + q];
                    mma16816(c, ah[mb], bh_[q]);   // hi*hi
                    mma16816(c, ah[mb], bl_[q]);   // hi*lo
                    mma16816(c, al[mb], bh_[q]);   // lo*hi
                }
        }
        buf ^= 1;
    }
}

// ---------------------------------------------------------------------------
// Epilogues
// ---------------------------------------------------------------------------
__device__ __forceinline__ void epi_split(
    const float acc[2][8][4], bf16* Ch, bf16* Cl, int ldc,
    int m0, int n0, bool tril)
{
    const int lane = threadIdx.x & 31, wid = threadIdx.x >> 5;
    const int g = lane >> 2, t = lane & 3;
    const int wm = (wid >> 1) * 32, wn = (wid & 1) * 64;
    #pragma unroll
    for (int mb = 0; mb < 2; mb++)
        #pragma unroll
        for (int nb = 0; nb < 8; nb++) {
            const int r0 = m0 + wm + mb * 16 + g, r1 = r0 + 8;
            const int c0 = n0 + wn + nb * 8 + t * 2;
            float v00 = acc[mb][nb][0], v01 = acc[mb][nb][1];
            float v10 = acc[mb][nb][2], v11 = acc[mb][nb][3];
            if (tril) {
                if (c0     > r0) v00 = 0.f;
                if (c0 + 1 > r0) v01 = 0.f;
                if (c0     > r1) v10 = 0.f;
                if (c0 + 1 > r1) v11 = 0.f;
            }
            bf16 h0, l0, h1, l1;
            split2(v00, h0, l0); split2(v01, h1, l1);
            __nv_bfloat162 ph; ph.x = h0; ph.y = h1;
            __nv_bfloat162 pl; pl.x = l0; pl.y = l1;
            *(__nv_bfloat162*)&Ch[(size_t)r0 * ldc + c0] = ph;
            *(__nv_bfloat162*)&Cl[(size_t)r0 * ldc + c0] = pl;
            split2(v10, h0, l0); split2(v11, h1, l1);
            ph.x = h0; ph.y = h1; pl.x = l0; pl.y = l1;
            *(__nv_bfloat162*)&Ch[(size_t)r1 * ldc + c0] = ph;
            *(__nv_bfloat162*)&Cl[(size_t)r1 * ldc + c0] = pl;
        }
}

__device__ __forceinline__ void epi_f32(
    const float acc[2][8][4], float* C, int ldc, int m0, int n0)
{
    const int lane = threadIdx.x & 31, wid = threadIdx.x >> 5;
    const int g = lane >> 2, t = lane & 3;
    const int wm = (wid >> 1) * 32, wn = (wid & 1) * 64;
    #pragma unroll
    for (int mb = 0; mb < 2; mb++)
        #pragma unroll
        for (int nb = 0; nb < 8; nb++) {
            const int r0 = m0 + wm + mb * 16 + g, r1 = r0 + 8;
            const int c0 = n0 + wn + nb * 8 + t * 2;
            *(float2*)&C[(size_t)r0 * ldc + c0] =
                make_float2(acc[mb][nb][0], acc[mb][nb][1]);
            *(float2*)&C[(size_t)r1 * ldc + c0] =
                make_float2(acc[mb][nb][2], acc[mb][nb][3]);
        }
}

#define ACC_DECL float acc[2][8][4];                        \
    _Pragma("unroll") for (int i_ = 0; i_ < 2; i_++)        \
    _Pragma("unroll") for (int j_ = 0; j_ < 8; j_++)        \
    _Pragma("unroll") for (int k_ = 0; k_ < 4; k_++) acc[i_][j_][k_] = 0.f;

// ---------------------------------------------------------------------------
// Prep kernels
// ---------------------------------------------------------------------------
__global__ void __launch_bounds__(256) k_prep_R(const float* __restrict__ R) {
    __shared__ bf16 sh[32][33], sl[32][33];
    const int b = blockIdx.z, i0 = blockIdx.x * 32, t0 = blockIdx.y * 32;
    const int tx = threadIdx.x, ty = threadIdx.y;    // (32,8)
    #pragma unroll
    for (int r = 0; r < 4; r++) {
        const int t = t0 + ty + r * 8;
        const size_t o = ((size_t)b * TN + t) * NN + i0 + tx;
        bf16 h, l; split2(R[o], h, l);
        g_Rh[o] = h; g_Rl[o] = l;
        sh[ty + r * 8][tx] = h; sl[ty + r * 8][tx] = l;
    }
    __syncthreads();
    #pragma unroll
    for (int r = 0; r < 4; r++) {
        const int i = i0 + ty + r * 8;
        const size_t o = ((size_t)b * NN + i) * TN + t0 + tx;
        g_Rth[o] = sh[tx][ty + r * 8];
        g_Rtl[o] = sl[tx][ty + r * 8];
    }
}

__global__ void __launch_bounds__(256) k_prep_Qt(const float* __restrict__ Q) {
    __shared__ bf16 sh[32][33], sl[32][33];
    const int h = blockIdx.z, j0 = blockIdx.x * 32, i0 = blockIdx.y * 32;
    const int tx = threadIdx.x, ty = threadIdx.y;
    #pragma unroll
    for (int r = 0; r < 4; r++) {
        const int i = i0 + ty + r * 8;
        bf16 hh, ll; split2(Q[((size_t)h * NN + i) * NN + j0 + tx], hh, ll);
        sh[ty + r * 8][tx] = hh; sl[ty + r * 8][tx] = ll;
    }
    __syncthreads();
    #pragma unroll
    for (int r = 0; r < 4; r++) {
        const int j = j0 + ty + r * 8;
        const size_t o = ((size_t)h * NN + j) * NN + i0 + tx;
        g_Qth[o] = sh[tx][ty + r * 8];
        g_Qtl[o] = sl[tx][ty + r * 8];
    }
}

__global__ void __launch_bounds__(256) k_prep_E(const float* __restrict__ E) {
    const size_t idx = (size_t)blockIdx.x * 256 + threadIdx.x;
    bf16 h, l; split2(E[idx], h, l);
    g_Eh[idx] = h; g_El[idx] = l;
}

// ---------------------------------------------------------------------------
// GEMM kernels
// ---------------------------------------------------------------------------
// A[bh] = R[b] @ Q[h]  :  X=R[t][i], Y^T=Qt[j][i]       grid (2,16,16)
__global__ void __launch_bounds__(256, 2) k_gemm_A() {
    __shared__ SB sb;
    const int z = blockIdx.z, b = z >> 3, h = z & 7;
    const int m0 = blockIdx.y * 128, n0 = blockIdx.x * 128;
    ACC_DECL
    gemm_ml(acc, &sb,
            g_Rh + ((size_t)b * TN + m0) * NN, g_Rl + ((size_t)b * TN + m0) * NN, NN,
            g_Qth + ((size_t)h * NN + n0) * NN, g_Qtl + ((size_t)h * NN + n0) * NN, NN,
            NN);
    epi_split(acc, g_Ah + (size_t)z * TN * NN, g_Al + (size_t)z * TN * NN,
              NN, m0, n0, false);
}

// Wt[bh][i][u] = E[h] @ R[b]^T (computed directly transposed)  grid (16,2,16)
__global__ void __launch_bounds__(256, 2) k_gemm_W() {
    __shared__ SB sb;
    const int z = blockIdx.z, b = z >> 3, h = z & 7;
    const int m0 = blockIdx.y * 128;   // i
    const int n0 = blockIdx.x * 128;   // u
    ACC_DECL
    gemm_ml(acc, &sb,
            g_Eh + ((size_t)h * NN + m0) * NN, g_El + ((size_t)h * NN + m0) * NN, NN,
            g_Rh + ((size_t)b * TN + n0) * NN, g_Rl + ((size_t)b * TN + n0) * NN, NN,
            NN);
    epi_split(acc, g_Wth + (size_t)z * NN * TN, g_Wtl + (size_t)z * NN * TN,
              TN, m0, n0, false);
}

// Gt[bhc][i][j] = sum_{u in chunk} Wt[i][u] Rt[j][u]    grid (2,2,128)
__global__ void __launch_bounds__(256, 2) k_gemm_Gt() {
    __shared__ SB sb;
    const int z = blockIdx.z, b = z >> 6, bh = z >> 3, c = z & 7;
    const int m0 = blockIdx.y * 128, n0 = blockIdx.x * 128;
    ACC_DECL
    gemm_ml(acc, &sb,
            g_Wth + (size_t)bh * NN * TN + (size_t)m0 * TN + c * CSZ,
            g_Wtl + (size_t)bh * NN * TN + (size_t)m0 * TN + c * CSZ, TN,
            g_Rth + (size_t)b * NN * TN + (size_t)n0 * TN + c * CSZ,
            g_Rtl + (size_t)b * NN * TN + (size_t)n0 * TN + c * CSZ, TN,
            CSZ);
    epi_f32(acc, g_Gt + (size_t)z * NN * NN, NN, m0, n0);
}

// St = exclusive prefix over chunks of Gt, split to bf16  grid 4096
__global__ void __launch_bounds__(256) k_prefix() {
    const size_t gid = (size_t)blockIdx.x * 256 + threadIdx.x;
    const size_t bh = gid >> 16, e = gid & 65535;
    float run = 0.f;
    #pragma unroll
    for (int c = 0; c < NCH; c++) {
        const size_t idx = (bh * NCH + c) * 65536 + e;
        bf16 h, l; split2(run, h, l);
        g_Sth[idx] = h; g_Stl[idx] = l;
        run += g_Gt[idx];
    }
}

// P[bhc] = tril(A_c @ R_c^T)  :  X=A[t][j], Y^T=R[u][j]  grid (2,2,128)
__global__ void __launch_bounds__(256, 2) k_gemm_P() {
    __shared__ SB sb;
    const int z = blockIdx.z, b = z >> 6, bh = z >> 3, c = z & 7;
    const int m0 = blockIdx.y * 128, n0 = blockIdx.x * 128;
    if (n0 > m0) return;   // fully above diagonal: never read downstream
    ACC_DECL
    gemm_ml(acc, &sb,
            g_Ah + (size_t)bh * TN * NN + (size_t)(c * CSZ + m0) * NN,
            g_Al + (size_t)bh * TN * NN + (size_t)(c * CSZ + m0) * NN, NN,
            g_Rh + (size_t)b * TN * NN + (size_t)(c * CSZ + n0) * NN,
            g_Rl + (size_t)b * TN * NN + (size_t)(c * CSZ + n0) * NN, NN,
            NN);
    epi_split(acc, g_Ph + (size_t)z * 65536, g_Pl + (size_t)z * 65536,
              NN, m0, n0, true);
}

// O[bh][chunk rows][i] = A_c @ S_c + P_c @ W_c  (fused dual-K)  grid (2,2,128)
__global__ void __launch_bounds__(256, 2) k_gemm_O() {
    __shared__ SB sb;
    const int z = blockIdx.z, bh = z >> 3, c = z & 7;
    const int m0 = blockIdx.y * 128, n0 = blockIdx.x * 128;  // m=t-local, n=i
    ACC_DECL
    if (c > 0) {   // inter-chunk: A @ S   (S=0 for c==0)
        gemm_ml(acc, &sb,
                g_Ah + (size_t)bh * TN * NN + (size_t)(c * CSZ + m0) * NN,
                g_Al + (size_t)bh * TN * NN + (size_t)(c * CSZ + m0) * NN, NN,
                g_Sth + ((size_t)bh * NCH + c) * 65536 + (size_t)n0 * NN,
                g_Stl + ((size_t)bh * NCH + c) * 65536 + (size_t)n0 * NN, NN,
                NN);
    }
    // intra-chunk: P @ W ; P rows m0.. have support only u <= m0+127
    gemm_ml(acc, &sb,
            g_Ph + (size_t)z * 65536 + (size_t)m0 * NN,
            g_Pl + (size_t)z * 65536 + (size_t)m0 * NN, NN,
            g_Wth + (size_t)bh * NN * TN + (size_t)n0 * TN + c * CSZ,
            g_Wtl + (size_t)bh * NN * TN + (size_t)n0 * TN + c * CSZ, TN,
            m0 + 128);
    epi_f32(acc, g_O + (size_t)bh * TN * NN + (size_t)c * CSZ * NN, NN, m0, n0);
}

// out[b,t,i] = sum_h O[b,h,t,i]   grid 4096
__global__ void __launch_bounds__(256) k_reduce(float* __restrict__ out) {
    const size_t gid = (size_t)blockIdx.x * 256 + threadIdx.x;
    const size_t b = gid / ((size_t)TN * NN);
    const size_t rem = gid % ((size_t)TN * NN);
    float s = 0.f;
    #pragma unroll
    for (int h = 0; h < HN; h++)
        s += g_O[((b * HN + h) * (size_t)TN * NN) + rem];
    out[gid] = s;
}

// ---------------------------------------------------------------------------
extern "C" void kernel_launch(void* const* d_in, const int* in_sizes, int n_in,
                              void* d_out, int out_size) {
    const float* R = (const float*)d_in[0];   // r_prime [2,2048,256]
    const float* Q = (const float*)d_in[1];   // Q       [8,256,256]
    const float* E = (const float*)d_in[2];   // E       [8,256,256]
    float* out = (float*)d_out;               // r       [2,2048,256]

    k_prep_R <<<dim3(8, 64, 2), dim3(32, 8)>>>(R);
    k_prep_Qt<<<dim3(8, 8, 8),  dim3(32, 8)>>>(Q);
    k_prep_E <<<2048, 256>>>(E);

    k_gemm_A <<<dim3(2, 16, 16), 256>>>();
    k_gemm_W <<<dim3(16, 2, 16), 256>>>();
    k_gemm_Gt<<<dim3(2, 2, 128), 256>>>();
    k_prefix <<<4096, 256>>>();
    k_gemm_P <<<dim3(2, 2, 128), 256>>>();
    k_gemm_O <<<dim3(2, 2, 128), 256>>>();
    k_reduce <<<4096, 256>>>(out);
}